// round 15
// baseline (speedup 1.0000x reference)
#include <cuda_runtime.h>
#include <cuda_fp16.h>
#include <math.h>
#include <stdint.h>

#define B_  4
#define S_  2048
#define D_  1024
#define H_  16
#define DH_ 64

// fp16 operand buffers
__device__ __half g_q[(size_t)B_ * H_ * S_ * DH_];    // pre-scaled by QSCALE
__device__ __half g_k[(size_t)B_ * H_ * S_ * DH_];
__device__ __half g_v[(size_t)B_ * H_ * S_ * DH_];
__device__ __half g_ctx[(size_t)B_ * S_ * D_];
__device__ __half g_xh[(size_t)B_ * S_ * D_];
__device__ __half g_wqh[(size_t)D_ * D_];
__device__ __half g_wkh[(size_t)D_ * D_];
__device__ __half g_wvh[(size_t)D_ * D_];
__device__ __half g_woh[(size_t)D_ * D_];

__device__ __forceinline__ float ex2(float x) {
    float r;
    asm("ex2.approx.f32 %0, %1;" : "=f"(r) : "f"(x));
    return r;
}

__device__ __forceinline__ uint32_t smem_u32(const void* p) {
    uint32_t a;
    asm("{ .reg .u64 t; cvta.to.shared.u64 t, %1; cvt.u32.u64 %0, t; }" : "=r"(a) : "l"(p));
    return a;
}

__device__ __forceinline__ void mma_f16(float c[4], uint32_t a0, uint32_t a1,
                                        uint32_t a2, uint32_t a3,
                                        uint32_t b0, uint32_t b1) {
    asm volatile(
        "mma.sync.aligned.m16n8k16.row.col.f32.f16.f16.f32 "
        "{%0,%1,%2,%3},{%4,%5,%6,%7},{%8,%9},{%0,%1,%2,%3};"
        : "+f"(c[0]), "+f"(c[1]), "+f"(c[2]), "+f"(c[3])
        : "r"(a0), "r"(a1), "r"(a2), "r"(a3), "r"(b0), "r"(b1));
}

__device__ __forceinline__ void ldsm4(uint32_t r[4], uint32_t addr) {
    asm volatile("ldmatrix.sync.aligned.m8n8.x4.shared.b16 {%0,%1,%2,%3}, [%4];"
                 : "=r"(r[0]), "=r"(r[1]), "=r"(r[2]), "=r"(r[3]) : "r"(addr));
}
__device__ __forceinline__ void ldsm4t(uint32_t r[4], uint32_t addr) {
    asm volatile("ldmatrix.sync.aligned.m8n8.x4.trans.shared.b16 {%0,%1,%2,%3}, [%4];"
                 : "=r"(r[0]), "=r"(r[1]), "=r"(r[2]), "=r"(r[3]) : "r"(addr));
}

__device__ __forceinline__ void cpasync16(uint32_t dst, const void* src) {
    asm volatile("cp.async.ca.shared.global [%0], [%1], 16;" :: "r"(dst), "l"(src) : "memory");
}
#define CP_COMMIT() asm volatile("cp.async.commit_group;" ::: "memory")
#define CP_WAIT0()  asm volatile("cp.async.wait_group 0;" ::: "memory")
#define CP_WAIT1()  asm volatile("cp.async.wait_group 1;" ::: "memory")

// ---------------------------------------------------------------------------
// Pre-convert (flat grid): fp32 -> fp16 for x and the four weight matrices.
// ---------------------------------------------------------------------------
#define XN4 ((B_ * S_ * D_) / 4)
#define WN4 ((D_ * D_) / 4)

__global__ void __launch_bounds__(256) preconv_kernel(const float* __restrict__ x,
                                                      const float* __restrict__ wq,
                                                      const float* __restrict__ wk,
                                                      const float* __restrict__ wv,
                                                      const float* __restrict__ wo)
{
    const int idx = blockIdx.x * 256 + threadIdx.x;
    const float* src;
    __half* dst;
    int off;
    if (idx < XN4) {
        src = x; dst = g_xh; off = idx;
    } else {
        const int widx = idx - XN4;
        const int region = widx / WN4;
        off = widx - region * WN4;
        switch (region) {
            case 0:  src = wq; dst = g_wqh; break;
            case 1:  src = wk; dst = g_wkh; break;
            case 2:  src = wv; dst = g_wvh; break;
            default: src = wo; dst = g_woh; break;
        }
    }
    float4 v = ((const float4*)src)[off];
    __half2 h0 = __floats2half2_rn(v.x, v.y);
    __half2 h1 = __floats2half2_rn(v.z, v.w);
    uint2 u;
    u.x = *(uint32_t*)&h0;
    u.y = *(uint32_t*)&h1;
    ((uint2*)dst)[off] = u;
}

// ---------------------------------------------------------------------------
// FP16 GEMM, ldmatrix-fed, 3-STAGE cp.async pipeline (wait_group 1).
// C[128,128] = A[128,1024]*W[128,1024]^T, BK=64 halfs, row stride 72 halfs.
// Schedule: wait(<=1) -> syncthreads -> prefetch(kc+2) -> compute(kc).
// Each load gets TWO chunk-computes of slack before its wait.
// ---------------------------------------------------------------------------
#define PBKH   64
#define PW2    72
#define PSTG_H (128 * PW2)
#define PNKH   (D_ / PBKH)

__device__ __forceinline__ void gemm_f16(const __half* __restrict__ A,
                                         const __half* __restrict__ W,
                                         float acc[4][4][4])
{
    extern __shared__ __half smh[];
    __half* Asm = smh;                    // [3][PSTG_H]
    __half* Bsm = smh + 3 * PSTG_H;       // [3][PSTG_H]

    const int tid  = threadIdx.x;
    const int lane = tid & 31;
    const int w    = tid >> 5;
    const int wm   = (w & 1) * 64;
    const int wn   = (w >> 1) * 32;

    const uint32_t sA = smem_u32(Asm);
    const uint32_t sB = smem_u32(Bsm);

    // ldmatrix lane->row/col mapping
    const int arow = (lane & 7) + ((lane >> 3) & 1) * 8;
    const int acol = ((lane >> 4) & 1) * 8;
    const int brow = (lane & 7) + ((lane >> 4) & 1) * 8;
    const int bcol = ((lane >> 3) & 1) * 8;
    uint32_t aoff[4], boff[2];
#pragma unroll
    for (int mt = 0; mt < 4; ++mt)
        aoff[mt] = (uint32_t)((wm + mt * 16 + arow) * PW2 + acol) * 2u;
#pragma unroll
    for (int p = 0; p < 2; ++p)
        boff[p] = (uint32_t)((wn + p * 16 + brow) * PW2 + bcol) * 2u;

    // Loader mapping
    int lrow[4], lcol[4];
    uint32_t ldst[4];
#pragma unroll
    for (int i = 0; i < 4; ++i) {
        const int L = tid + 256 * i;
        lrow[i] = L >> 3;
        lcol[i] = (L & 7) << 3;
        ldst[i] = (uint32_t)(lrow[i] * PW2 + lcol[i]) * 2u;
    }

#pragma unroll
    for (int mt = 0; mt < 4; ++mt)
#pragma unroll
        for (int nt = 0; nt < 4; ++nt)
#pragma unroll
            for (int c = 0; c < 4; ++c) acc[mt][nt][c] = 0.0f;

    // Prologue: chunks 0,1 into bufs 0,1 (two groups)
#pragma unroll
    for (int s = 0; s < 2; ++s) {
        const uint32_t bb = (uint32_t)(s * PSTG_H) * 2u;
        const int ko = s * PBKH;
#pragma unroll
        for (int i = 0; i < 4; ++i) {
            cpasync16(sA + bb + ldst[i], A + (size_t)lrow[i] * D_ + ko + lcol[i]);
            cpasync16(sB + bb + ldst[i], W + (size_t)lrow[i] * D_ + ko + lcol[i]);
        }
        CP_COMMIT();
    }

#pragma unroll 1
    for (int kc = 0; kc < PNKH; ++kc) {
        if (kc < PNKH - 1) CP_WAIT1(); else CP_WAIT0();
        __syncthreads();   // publish chunk kc; prove buf (kc+2)%3 readers done

        if (kc + 2 < PNKH) {
            const int nb = (kc + 2) - ((kc + 2) / 3) * 3;
            const uint32_t bb = (uint32_t)(nb * PSTG_H) * 2u;
            const int ko = (kc + 2) * PBKH;
#pragma unroll
            for (int i = 0; i < 4; ++i) {
                cpasync16(sA + bb + ldst[i], A + (size_t)lrow[i] * D_ + ko + lcol[i]);
                cpasync16(sB + bb + ldst[i], W + (size_t)lrow[i] * D_ + ko + lcol[i]);
            }
            CP_COMMIT();
        }

        const int buf = kc - (kc / 3) * 3;
        const uint32_t aB = sA + (uint32_t)(buf * PSTG_H) * 2u;
        const uint32_t bB = sB + (uint32_t)(buf * PSTG_H) * 2u;

#pragma unroll
        for (int ks = 0; ks < 4; ++ks) {
            const uint32_t kb = (uint32_t)(ks * 16) * 2u;
            uint32_t bq[2][4];
            ldsm4(bq[0], bB + boff[0] + kb);
            ldsm4(bq[1], bB + boff[1] + kb);
#pragma unroll
            for (int mt = 0; mt < 4; ++mt) {
                uint32_t aq[4];
                ldsm4(aq, aB + aoff[mt] + kb);
                mma_f16(acc[mt][0], aq[0], aq[1], aq[2], aq[3], bq[0][0], bq[0][1]);
                mma_f16(acc[mt][1], aq[0], aq[1], aq[2], aq[3], bq[0][2], bq[0][3]);
                mma_f16(acc[mt][2], aq[0], aq[1], aq[2], aq[3], bq[1][0], bq[1][1]);
                mma_f16(acc[mt][3], aq[0], aq[1], aq[2], aq[3], bq[1][2], bq[1][3]);
            }
        }
    }
}

#define QSCALE 0.180336887f   // 0.125 * log2(e)

// ---------------------------------------------------------------------------
// Fused QKV projection + RoPE epilogue (fp16 out; q pre-scaled by QSCALE).
// ---------------------------------------------------------------------------
__global__ void __launch_bounds__(256, 2) qkv_gemm_kernel(const int* __restrict__ pos)
{
    __shared__ float s_inv[32];
    if (threadIdx.x < 32)
        s_inv[threadIdx.x] = powf(10000.0f, -((float)(threadIdx.x * 2)) / 64.0f);

    const int m0 = blockIdx.y << 7;
    const int n0 = blockIdx.x << 7;
    const __half* W = (blockIdx.z == 0) ? g_wqh : ((blockIdx.z == 1) ? g_wkh : g_wvh);
    __half* out    = (blockIdx.z == 0) ? g_q : ((blockIdx.z == 1) ? g_k : g_v);
    const bool doRope = (blockIdx.z < 2);
    const float oscale = (blockIdx.z == 0) ? QSCALE : 1.0f;

    float acc[4][4][4];
    gemm_f16(g_xh + (size_t)m0 * D_, W + (size_t)n0 * D_, acc);

    const int lane = threadIdx.x & 31;
    const int w    = threadIdx.x >> 5;
    const int wm   = (w & 1) * 64;
    const int wn   = (w >> 1) * 32;
    const int g    = lane >> 2;
    const int tg   = lane & 3;

#pragma unroll
    for (int mt = 0; mt < 4; ++mt) {
#pragma unroll
        for (int half = 0; half < 2; ++half) {
            const int m = m0 + wm + mt * 16 + g + half * 8;
            const int b = m >> 11;
            const int s = m & (S_ - 1);
            const float fpos = doRope ? (float)pos[b * S_ + s] : 0.0f;
#pragma unroll
            for (int nt = 0; nt < 4; ++nt) {
                const int n  = n0 + wn + nt * 8 + tg * 2;
                const int h  = n >> 6;
                const int dh = n & 63;
                float vx = acc[mt][nt][half * 2 + 0];
                float vy = acc[mt][nt][half * 2 + 1];
                if (doRope) {
                    const float ang = fpos * s_inv[dh >> 1];
                    float sn, cs;
                    sincosf(ang, &sn, &cs);
                    const float rx = vx * cs - vy * sn;
                    const float ry = vx * sn + vy * cs;
                    vx = rx; vy = ry;
                }
                vx *= oscale; vy *= oscale;
                __half2 hv = __floats2half2_rn(vx, vy);
                *(uint32_t*)&out[((((size_t)b * H_ + h) * S_ + s) << 6) + dh] = *(uint32_t*)&hv;
            }
        }
    }
}

// ---------------------------------------------------------------------------
// Output projection (fp16 in, fp32 out).
// ---------------------------------------------------------------------------
__global__ void __launch_bounds__(256, 2) oproj_gemm_kernel(float* __restrict__ Out)
{
    const int m0 = blockIdx.y << 7;
    const int n0 = blockIdx.x << 7;

    float acc[4][4][4];
    gemm_f16(g_ctx + (size_t)m0 * D_, g_woh + (size_t)n0 * D_, acc);

    const int lane = threadIdx.x & 31;
    const int w    = threadIdx.x >> 5;
    const int wm   = (w & 1) * 64;
    const int wn   = (w >> 1) * 32;
    const int g    = lane >> 2;
    const int tg   = lane & 3;

#pragma unroll
    for (int mt = 0; mt < 4; ++mt) {
#pragma unroll
        for (int nt = 0; nt < 4; ++nt) {
            const int n = n0 + wn + nt * 8 + tg * 2;
#pragma unroll
            for (int half = 0; half < 2; ++half) {
                const int m = m0 + wm + mt * 16 + g + half * 8;
                float2 v;
                v.x = acc[mt][nt][half * 2 + 0];
                v.y = acc[mt][nt][half * 2 + 1];
                *(float2*)&Out[(size_t)m * D_ + n] = v;
            }
        }
    }
}

// ---------------------------------------------------------------------------
// Flash attention (causal, fp16 mma, ldmatrix-fed), double-buffered K/V,
// 3 CTAs/SM target (launch_bounds(128,3), regs <= 170).
// ---------------------------------------------------------------------------
__global__ void __launch_bounds__(128, 3) attn_kernel()
{
    extern __shared__ __half smha[];
    __half* Qs = smha;                     // [128][72]
    __half* Ks = Qs + 128 * PW2;           // [2][64][72]
    __half* Vs = Ks + 2 * 64 * PW2;        // [2][64][72]
    __half* Ps = Vs + 2 * 64 * PW2;        // [128][72]

    const int bh = blockIdx.x;
    const int qt = gridDim.y - 1 - blockIdx.y;   // heavy tiles first
    const int q0 = qt << 7;

    const __half* Qg = g_q + ((size_t)bh * S_ << 6);
    const __half* Kg = g_k + ((size_t)bh * S_ << 6);
    const __half* Vg = g_v + ((size_t)bh * S_ << 6);

    const int tid  = threadIdx.x;
    const int lane = tid & 31;
    const int w    = tid >> 5;
    const int g    = lane >> 2;
    const int tg   = lane & 3;
    const int rw   = w << 5;

    const uint32_t sQ = smem_u32(Qs);
    const uint32_t sK = smem_u32(Ks);
    const uint32_t sV = smem_u32(Vs);
    const uint32_t sP = smem_u32(Ps);
    const uint32_t KVSTEP = (uint32_t)(64 * PW2) * 2u;

    // ldmatrix offsets
    const int arow = (lane & 7) + ((lane >> 3) & 1) * 8;
    const int acol = ((lane >> 4) & 1) * 8;
    const int brow = (lane & 7) + ((lane >> 4) & 1) * 8;
    const int bcol = ((lane >> 3) & 1) * 8;
    const int vrow = (lane & 7) + ((lane >> 3) & 1) * 8;
    const int vcol = ((lane >> 4) & 1) * 8;

    uint32_t qoff[2], koff[4], voff[4];
#pragma unroll
    for (int mt = 0; mt < 2; ++mt)
        qoff[mt] = (uint32_t)((rw + mt * 16 + arow) * PW2 + acol) * 2u;
#pragma unroll
    for (int p = 0; p < 4; ++p) {
        koff[p] = (uint32_t)((p * 16 + brow) * PW2 + bcol) * 2u;
        voff[p] = (uint32_t)(vrow * PW2 + p * 16 + vcol) * 2u;
    }

    // Loader mapping for K/V tiles
    int krow[4], kcol[4];
    uint32_t kdst[4];
#pragma unroll
    for (int i = 0; i < 4; ++i) {
        const int L = tid + (i << 7);
        krow[i] = L >> 3;
        kcol[i] = (L & 7) << 3;
        kdst[i] = (uint32_t)(krow[i] * PW2 + kcol[i]) * 2u;
    }

    // Prologue: stage Q + K/V tile 0
#pragma unroll
    for (int i = 0; i < 8; ++i) {
        const int L = tid + (i << 7);
        const int row = L >> 3;
        const int col = (L & 7) << 3;
        cpasync16(sQ + (uint32_t)(row * PW2 + col) * 2u,
                  Qg + ((size_t)(q0 + row) << 6) + col);
    }
#pragma unroll
    for (int i = 0; i < 4; ++i) {
        cpasync16(sK + kdst[i], Kg + ((size_t)krow[i] << 6) + kcol[i]);
        cpasync16(sV + kdst[i], Vg + ((size_t)krow[i] << 6) + kcol[i]);
    }
    CP_COMMIT();

    float o[2][8][4];
#pragma unroll
    for (int mt = 0; mt < 2; ++mt)
#pragma unroll
        for (int nt = 0; nt < 8; ++nt)
#pragma unroll
            for (int c = 0; c < 4; ++c) o[mt][nt][c] = 0.0f;
    float mrow[2][2], lrow[2][2];
#pragma unroll
    for (int mt = 0; mt < 2; ++mt) {
        mrow[mt][0] = -1e30f; mrow[mt][1] = -1e30f;
        lrow[mt][0] = 0.0f;   lrow[mt][1] = 0.0f;
    }

    const int nkt = 2 * qt + 2;
#pragma unroll 1
    for (int kt = 0; kt < nkt; ++kt) {
        const int k0 = kt << 6;

        CP_WAIT0();
        __syncthreads();

        if (kt + 1 < nkt) {
            const uint32_t bb = (uint32_t)((kt + 1) & 1) * KVSTEP;
            const int kn = (kt + 1) << 6;
#pragma unroll
            for (int i = 0; i < 4; ++i) {
                cpasync16(sK + bb + kdst[i], Kg + ((size_t)(kn + krow[i]) << 6) + kcol[i]);
                cpasync16(sV + bb + kdst[i], Vg + ((size_t)(kn + krow[i]) << 6) + kcol[i]);
            }
            CP_COMMIT();
        }

        const uint32_t kBuf = sK + (uint32_t)(kt & 1) * KVSTEP;
        const uint32_t vBuf = sV + (uint32_t)(kt & 1) * KVSTEP;

        // Scores (log2 domain)
        float acc[2][8][4];
#pragma unroll
        for (int mt = 0; mt < 2; ++mt)
#pragma unroll
            for (int nt = 0; nt < 8; ++nt)
#pragma unroll
                for (int c = 0; c < 4; ++c) acc[mt][nt][c] = 0.0f;

#pragma unroll
        for (int ks = 0; ks < 4; ++ks) {
            const uint32_t kb = (uint32_t)(ks * 16) * 2u;
            uint32_t kq[4][4];
#pragma unroll
            for (int p = 0; p < 4; ++p) ldsm4(kq[p], kBuf + koff[p] + kb);
#pragma unroll
            for (int mt = 0; mt < 2; ++mt) {
                uint32_t aq[4];
                ldsm4(aq, sQ + qoff[mt] + kb);
#pragma unroll
                for (int nt = 0; nt < 8; ++nt)
                    mma_f16(acc[mt][nt], aq[0], aq[1], aq[2], aq[3],
                            kq[nt >> 1][(nt & 1) * 2], kq[nt >> 1][(nt & 1) * 2 + 1]);
            }
        }

        // Causal mask
        if (kt >= 2 * qt) {
#pragma unroll
            for (int mt = 0; mt < 2; ++mt) {
                const int row0 = q0 + rw + (mt << 4) + g;
                const int row1 = row0 + 8;
#pragma unroll
                for (int nt = 0; nt < 8; ++nt) {
#pragma unroll
                    for (int cc = 0; cc < 2; ++cc) {
                        const int col = k0 + nt * 8 + tg * 2 + cc;
                        if (col > row0) acc[mt][nt][cc]     = -1e30f;
                        if (col > row1) acc[mt][nt][cc + 2] = -1e30f;
                    }
                }
            }
        }

        // Register online softmax (log2 domain; quad shfl)
#pragma unroll
        for (int mt = 0; mt < 2; ++mt) {
            const int rA = rw + (mt << 4) + g;
            const int rB = rA + 8;
            float mx0 = -1e30f, mx1 = -1e30f;
#pragma unroll
            for (int nt = 0; nt < 8; ++nt) {
                mx0 = fmaxf(mx0, fmaxf(acc[mt][nt][0], acc[mt][nt][1]));
                mx1 = fmaxf(mx1, fmaxf(acc[mt][nt][2], acc[mt][nt][3]));
            }
            mx0 = fmaxf(mx0, __shfl_xor_sync(0xffffffffu, mx0, 1));
            mx0 = fmaxf(mx0, __shfl_xor_sync(0xffffffffu, mx0, 2));
            mx1 = fmaxf(mx1, __shfl_xor_sync(0xffffffffu, mx1, 1));
            mx1 = fmaxf(mx1, __shfl_xor_sync(0xffffffffu, mx1, 2));

            const float mn0 = fmaxf(mrow[mt][0], mx0);
            const float mn1 = fmaxf(mrow[mt][1], mx1);
            const float sc0 = ex2(mrow[mt][0] - mn0);
            const float sc1 = ex2(mrow[mt][1] - mn1);

            float rs0 = 0.0f, rs1 = 0.0f;
#pragma unroll
            for (int nt = 0; nt < 8; ++nt) {
                const float p00 = ex2(acc[mt][nt][0] - mn0);
                const float p01 = ex2(acc[mt][nt][1] - mn0);
                const float p10 = ex2(acc[mt][nt][2] - mn1);
                const float p11 = ex2(acc[mt][nt][3] - mn1);
                rs0 += p00 + p01;
                rs1 += p10 + p11;
                const int cb = nt * 8 + tg * 2;
                __half2 hA = __floats2half2_rn(p00, p01);
                __half2 hB = __floats2half2_rn(p10, p11);
                *(uint32_t*)&Ps[rA * PW2 + cb] = *(uint32_t*)&hA;
                *(uint32_t*)&Ps[rB * PW2 + cb] = *(uint32_t*)&hB;
            }
            rs0 += __shfl_xor_sync(0xffffffffu, rs0, 1);
            rs0 += __shfl_xor_sync(0xffffffffu, rs0, 2);
            rs1 += __shfl_xor_sync(0xffffffffu, rs1, 1);
            rs1 += __shfl_xor_sync(0xffffffffu, rs1, 2);

            lrow[mt][0] = lrow[mt][0] * sc0 + rs0;
            lrow[mt][1] = lrow[mt][1] * sc1 + rs1;
            mrow[mt][0] = mn0;
            mrow[mt][1] = mn1;

#pragma unroll
            for (int nt = 0; nt < 8; ++nt) {
                o[mt][nt][0] *= sc0; o[mt][nt][1] *= sc0;
                o[mt][nt][2] *= sc1; o[mt][nt][3] *= sc1;
            }
        }

        __syncwarp();

        // PV: P via ldsm4, V via ldsm4t (trans)
#pragma unroll
        for (int js = 0; js < 4; ++js) {
            const uint32_t jb = (uint32_t)(js * 16) * 2u;
            const uint32_t vb = (uint32_t)(js * 16 * PW2) * 2u;
            uint32_t vq[4][4];
#pragma unroll
            for (int p = 0; p < 4; ++p) ldsm4t(vq[p], vBuf + voff[p] + vb);
#pragma unroll
            for (int mt = 0; mt < 2; ++mt) {
                uint32_t aq[4];
                ldsm4(aq, sP + qoff[mt] + jb);
#pragma unroll
                for (int nt = 0; nt < 8; ++nt)
                    mma_f16(o[mt][nt], aq[0], aq[1], aq[2], aq[3],
                            vq[nt >> 1][(nt & 1) * 2], vq[nt >> 1][(nt & 1) * 2 + 1]);
            }
        }
    }

    // Epilogue -> ctx fp16
    const int b = bh >> 4;
    const int h = bh & 15;
#pragma unroll
    for (int mt = 0; mt < 2; ++mt) {
        const int rA = rw + (mt << 4) + g;
        const int rB = rA + 8;
        const float invl0 = 1.0f / lrow[mt][0];
        const float invl1 = 1.0f / lrow[mt][1];
#pragma unroll
        for (int nt = 0; nt < 8; ++nt) {
            const int col = (h << 6) + nt * 8 + tg * 2;
            __half2 h0 = __floats2half2_rn(o[mt][nt][0] * invl0, o[mt][nt][1] * invl0);
            __half2 h1 = __floats2half2_rn(o[mt][nt][2] * invl1, o[mt][nt][3] * invl1);
            *(uint32_t*)&g_ctx[((size_t)(b * S_ + q0 + rA)) * D_ + col] = *(uint32_t*)&h0;
            *(uint32_t*)&g_ctx[((size_t)(b * S_ + q0 + rB)) * D_ + col] = *(uint32_t*)&h1;
        }
    }
}

// ---------------------------------------------------------------------------
// Host launcher
// ---------------------------------------------------------------------------
extern "C" void kernel_launch(void* const* d_in, const int* in_sizes, int n_in,
                              void* d_out, int out_size)
{
    const float* x   = (const float*)d_in[0];
    const int*   pos = (const int*)  d_in[1];
    const float* Wq  = (const float*)d_in[2];
    const float* Wk  = (const float*)d_in[3];
    const float* Wv  = (const float*)d_in[4];
    const float* Wo  = (const float*)d_in[5];
    float* out = (float*)d_out;

    const int PROJ_SMEM = 6 * PSTG_H * sizeof(__half);                          // 110592 B
    const int ATTN_SMEM = (128 + 2 * 64 + 2 * 64 + 128) * PW2 * sizeof(__half); // 73728 B

    cudaFuncSetAttribute(qkv_gemm_kernel,   cudaFuncAttributeMaxDynamicSharedMemorySize, PROJ_SMEM);
    cudaFuncSetAttribute(oproj_gemm_kernel, cudaFuncAttributeMaxDynamicSharedMemorySize, PROJ_SMEM);
    cudaFuncSetAttribute(attn_kernel,       cudaFuncAttributeMaxDynamicSharedMemorySize, ATTN_SMEM);

    const int PRE_CTAS = (XN4 + 4 * WN4) / 256;   // 12288
    preconv_kernel<<<PRE_CTAS, 256>>>(x, Wq, Wk, Wv, Wo);
    qkv_gemm_kernel<<<dim3(D_ / 128, (B_ * S_) / 128, 3), 256, PROJ_SMEM>>>(pos);
    attn_kernel<<<dim3(B_ * H_, S_ / 128), 128, ATTN_SMEM>>>();
    oproj_gemm_kernel<<<dim3(D_ / 128, (B_ * S_) / 128), 256, PROJ_SMEM>>>(out);
}

// round 16
// speedup vs baseline: 1.0927x; 1.0927x over previous
#include <cuda_runtime.h>
#include <cuda_fp16.h>
#include <math.h>
#include <stdint.h>

#define B_  4
#define S_  2048
#define D_  1024
#define H_  16
#define DH_ 64

// fp16 operand buffers
__device__ __half g_q[(size_t)B_ * H_ * S_ * DH_];    // pre-scaled by QSCALE
__device__ __half g_k[(size_t)B_ * H_ * S_ * DH_];
__device__ __half g_v[(size_t)B_ * H_ * S_ * DH_];
__device__ __half g_ctx[(size_t)B_ * S_ * D_];
__device__ __half g_xh[(size_t)B_ * S_ * D_];
__device__ __half g_wqh[(size_t)D_ * D_];
__device__ __half g_wkh[(size_t)D_ * D_];
__device__ __half g_wvh[(size_t)D_ * D_];
__device__ __half g_woh[(size_t)D_ * D_];

__device__ __forceinline__ float ex2(float x) {
    float r;
    asm("ex2.approx.f32 %0, %1;" : "=f"(r) : "f"(x));
    return r;
}

__device__ __forceinline__ uint32_t smem_u32(const void* p) {
    uint32_t a;
    asm("{ .reg .u64 t; cvta.to.shared.u64 t, %1; cvt.u32.u64 %0, t; }" : "=r"(a) : "l"(p));
    return a;
}

__device__ __forceinline__ void mma_f16(float c[4], uint32_t a0, uint32_t a1,
                                        uint32_t a2, uint32_t a3,
                                        uint32_t b0, uint32_t b1) {
    asm volatile(
        "mma.sync.aligned.m16n8k16.row.col.f32.f16.f16.f32 "
        "{%0,%1,%2,%3},{%4,%5,%6,%7},{%8,%9},{%0,%1,%2,%3};"
        : "+f"(c[0]), "+f"(c[1]), "+f"(c[2]), "+f"(c[3])
        : "r"(a0), "r"(a1), "r"(a2), "r"(a3), "r"(b0), "r"(b1));
}

__device__ __forceinline__ void ldsm4(uint32_t r[4], uint32_t addr) {
    asm volatile("ldmatrix.sync.aligned.m8n8.x4.shared.b16 {%0,%1,%2,%3}, [%4];"
                 : "=r"(r[0]), "=r"(r[1]), "=r"(r[2]), "=r"(r[3]) : "r"(addr));
}
__device__ __forceinline__ void ldsm4t(uint32_t r[4], uint32_t addr) {
    asm volatile("ldmatrix.sync.aligned.m8n8.x4.trans.shared.b16 {%0,%1,%2,%3}, [%4];"
                 : "=r"(r[0]), "=r"(r[1]), "=r"(r[2]), "=r"(r[3]) : "r"(addr));
}

__device__ __forceinline__ void cpasync16(uint32_t dst, const void* src) {
    asm volatile("cp.async.ca.shared.global [%0], [%1], 16;" :: "r"(dst), "l"(src) : "memory");
}
#define CP_COMMIT() asm volatile("cp.async.commit_group;" ::: "memory")
#define CP_WAIT0()  asm volatile("cp.async.wait_group 0;" ::: "memory")

// ---------------------------------------------------------------------------
// Pre-convert (flat grid): fp32 -> fp16 for x and the four weight matrices.
// ---------------------------------------------------------------------------
#define XN4 ((B_ * S_ * D_) / 4)
#define WN4 ((D_ * D_) / 4)

__global__ void __launch_bounds__(256) preconv_kernel(const float* __restrict__ x,
                                                      const float* __restrict__ wq,
                                                      const float* __restrict__ wk,
                                                      const float* __restrict__ wv,
                                                      const float* __restrict__ wo)
{
    const int idx = blockIdx.x * 256 + threadIdx.x;
    const float* src;
    __half* dst;
    int off;
    if (idx < XN4) {
        src = x; dst = g_xh; off = idx;
    } else {
        const int widx = idx - XN4;
        const int region = widx / WN4;
        off = widx - region * WN4;
        switch (region) {
            case 0:  src = wq; dst = g_wqh; break;
            case 1:  src = wk; dst = g_wkh; break;
            case 2:  src = wv; dst = g_wvh; break;
            default: src = wo; dst = g_woh; break;
        }
    }
    float4 v = ((const float4*)src)[off];
    __half2 h0 = __floats2half2_rn(v.x, v.y);
    __half2 h1 = __floats2half2_rn(v.z, v.w);
    uint2 u;
    u.x = *(uint32_t*)&h0;
    u.y = *(uint32_t*)&h1;
    ((uint2*)dst)[off] = u;
}

// ---------------------------------------------------------------------------
// FP16 GEMM (R14 version — measured fastest), ldmatrix-fed, 1-barrier
// 2-stage cp.async double buffering.
// ---------------------------------------------------------------------------
#define PBKH   64
#define PW2    72
#define PSTG_H (128 * PW2)
#define PNKH   (D_ / PBKH)

__device__ __forceinline__ void gemm_f16(const __half* __restrict__ A,
                                         const __half* __restrict__ W,
                                         float acc[4][4][4])
{
    extern __shared__ __half smh[];
    __half* Asm = smh;
    __half* Bsm = smh + 2 * PSTG_H;

    const int tid  = threadIdx.x;
    const int lane = tid & 31;
    const int w    = tid >> 5;
    const int wm   = (w & 1) * 64;
    const int wn   = (w >> 1) * 32;

    const uint32_t sA = smem_u32(Asm);
    const uint32_t sB = smem_u32(Bsm);

    const int arow = (lane & 7) + ((lane >> 3) & 1) * 8;
    const int acol = ((lane >> 4) & 1) * 8;
    const int brow = (lane & 7) + ((lane >> 4) & 1) * 8;
    const int bcol = ((lane >> 3) & 1) * 8;
    uint32_t aoff[4], boff[2];
#pragma unroll
    for (int mt = 0; mt < 4; ++mt)
        aoff[mt] = (uint32_t)((wm + mt * 16 + arow) * PW2 + acol) * 2u;
#pragma unroll
    for (int p = 0; p < 2; ++p)
        boff[p] = (uint32_t)((wn + p * 16 + brow) * PW2 + bcol) * 2u;

    int lrow[4], lcol[4];
    uint32_t ldst[4];
#pragma unroll
    for (int i = 0; i < 4; ++i) {
        const int L = tid + 256 * i;
        lrow[i] = L >> 3;
        lcol[i] = (L & 7) << 3;
        ldst[i] = (uint32_t)(lrow[i] * PW2 + lcol[i]) * 2u;
    }

#pragma unroll
    for (int mt = 0; mt < 4; ++mt)
#pragma unroll
        for (int nt = 0; nt < 4; ++nt)
#pragma unroll
            for (int c = 0; c < 4; ++c) acc[mt][nt][c] = 0.0f;

#pragma unroll
    for (int i = 0; i < 4; ++i) {
        cpasync16(sA + ldst[i], A + (size_t)lrow[i] * D_ + lcol[i]);
        cpasync16(sB + ldst[i], W + (size_t)lrow[i] * D_ + lcol[i]);
    }
    CP_COMMIT();

#pragma unroll 1
    for (int kc = 0; kc < PNKH; ++kc) {
        CP_WAIT0();
        __syncthreads();

        if (kc + 1 < PNKH) {
            const uint32_t bb = (uint32_t)(((kc + 1) & 1) * PSTG_H) * 2u;
            const int ko = (kc + 1) * PBKH;
#pragma unroll
            for (int i = 0; i < 4; ++i) {
                cpasync16(sA + bb + ldst[i], A + (size_t)lrow[i] * D_ + ko + lcol[i]);
                cpasync16(sB + bb + ldst[i], W + (size_t)lrow[i] * D_ + ko + lcol[i]);
            }
            CP_COMMIT();
        }

        const uint32_t aB = sA + (uint32_t)((kc & 1) * PSTG_H) * 2u;
        const uint32_t bB = sB + (uint32_t)((kc & 1) * PSTG_H) * 2u;

#pragma unroll
        for (int ks = 0; ks < 4; ++ks) {
            const uint32_t kb = (uint32_t)(ks * 16) * 2u;
            uint32_t bq[2][4];
            ldsm4(bq[0], bB + boff[0] + kb);
            ldsm4(bq[1], bB + boff[1] + kb);
#pragma unroll
            for (int mt = 0; mt < 4; ++mt) {
                uint32_t aq[4];
                ldsm4(aq, aB + aoff[mt] + kb);
                mma_f16(acc[mt][0], aq[0], aq[1], aq[2], aq[3], bq[0][0], bq[0][1]);
                mma_f16(acc[mt][1], aq[0], aq[1], aq[2], aq[3], bq[0][2], bq[0][3]);
                mma_f16(acc[mt][2], aq[0], aq[1], aq[2], aq[3], bq[1][0], bq[1][1]);
                mma_f16(acc[mt][3], aq[0], aq[1], aq[2], aq[3], bq[1][2], bq[1][3]);
            }
        }
    }
}

#define QSCALE 0.180336887f   // 0.125 * log2(e)

// ---------------------------------------------------------------------------
// Fused QKV projection + RoPE epilogue (fp16 out; q pre-scaled by QSCALE).
// ---------------------------------------------------------------------------
__global__ void __launch_bounds__(256, 2) qkv_gemm_kernel(const int* __restrict__ pos)
{
    __shared__ float s_inv[32];
    if (threadIdx.x < 32)
        s_inv[threadIdx.x] = powf(10000.0f, -((float)(threadIdx.x * 2)) / 64.0f);

    const int m0 = blockIdx.y << 7;
    const int n0 = blockIdx.x << 7;
    const __half* W = (blockIdx.z == 0) ? g_wqh : ((blockIdx.z == 1) ? g_wkh : g_wvh);
    __half* out    = (blockIdx.z == 0) ? g_q : ((blockIdx.z == 1) ? g_k : g_v);
    const bool doRope = (blockIdx.z < 2);
    const float oscale = (blockIdx.z == 0) ? QSCALE : 1.0f;

    float acc[4][4][4];
    gemm_f16(g_xh + (size_t)m0 * D_, W + (size_t)n0 * D_, acc);

    const int lane = threadIdx.x & 31;
    const int w    = threadIdx.x >> 5;
    const int wm   = (w & 1) * 64;
    const int wn   = (w >> 1) * 32;
    const int g    = lane >> 2;
    const int tg   = lane & 3;

#pragma unroll
    for (int mt = 0; mt < 4; ++mt) {
#pragma unroll
        for (int half = 0; half < 2; ++half) {
            const int m = m0 + wm + mt * 16 + g + half * 8;
            const int b = m >> 11;
            const int s = m & (S_ - 1);
            const float fpos = doRope ? (float)pos[b * S_ + s] : 0.0f;
#pragma unroll
            for (int nt = 0; nt < 4; ++nt) {
                const int n  = n0 + wn + nt * 8 + tg * 2;
                const int h  = n >> 6;
                const int dh = n & 63;
                float vx = acc[mt][nt][half * 2 + 0];
                float vy = acc[mt][nt][half * 2 + 1];
                if (doRope) {
                    const float ang = fpos * s_inv[dh >> 1];
                    float sn, cs;
                    sincosf(ang, &sn, &cs);
                    const float rx = vx * cs - vy * sn;
                    const float ry = vx * sn + vy * cs;
                    vx = rx; vy = ry;
                }
                vx *= oscale; vy *= oscale;
                __half2 hv = __floats2half2_rn(vx, vy);
                *(uint32_t*)&out[((((size_t)b * H_ + h) * S_ + s) << 6) + dh] = *(uint32_t*)&hv;
            }
        }
    }
}

// ---------------------------------------------------------------------------
// Output projection (fp16 in, fp32 out).
// ---------------------------------------------------------------------------
__global__ void __launch_bounds__(256, 2) oproj_gemm_kernel(float* __restrict__ Out)
{
    const int m0 = blockIdx.y << 7;
    const int n0 = blockIdx.x << 7;

    float acc[4][4][4];
    gemm_f16(g_ctx + (size_t)m0 * D_, g_woh + (size_t)n0 * D_, acc);

    const int lane = threadIdx.x & 31;
    const int w    = threadIdx.x >> 5;
    const int wm   = (w & 1) * 64;
    const int wn   = (w >> 1) * 32;
    const int g    = lane >> 2;
    const int tg   = lane & 3;

#pragma unroll
    for (int mt = 0; mt < 4; ++mt) {
#pragma unroll
        for (int nt = 0; nt < 4; ++nt) {
            const int n = n0 + wn + nt * 8 + tg * 2;
#pragma unroll
            for (int half = 0; half < 2; ++half) {
                const int m = m0 + wm + mt * 16 + g + half * 8;
                float2 v;
                v.x = acc[mt][nt][half * 2 + 0];
                v.y = acc[mt][nt][half * 2 + 1];
                *(float2*)&Out[(size_t)m * D_ + n] = v;
            }
        }
    }
}

// ---------------------------------------------------------------------------
// Flash attention (R14 base: double-buffered K/V, (128,2)) + register-level
// fragment prefetch: next k-step's K/V fragments load before current mmas.
// ---------------------------------------------------------------------------
__global__ void __launch_bounds__(128, 2) attn_kernel()
{
    extern __shared__ __half smha[];
    __half* Qs = smha;                     // [128][72]
    __half* Ks = Qs + 128 * PW2;           // [2][64][72]
    __half* Vs = Ks + 2 * 64 * PW2;        // [2][64][72]
    __half* Ps = Vs + 2 * 64 * PW2;        // [128][72]

    const int bh = blockIdx.x;
    const int qt = gridDim.y - 1 - blockIdx.y;   // heavy tiles first
    const int q0 = qt << 7;

    const __half* Qg = g_q + ((size_t)bh * S_ << 6);
    const __half* Kg = g_k + ((size_t)bh * S_ << 6);
    const __half* Vg = g_v + ((size_t)bh * S_ << 6);

    const int tid  = threadIdx.x;
    const int lane = tid & 31;
    const int w    = tid >> 5;
    const int g    = lane >> 2;
    const int tg   = lane & 3;
    const int rw   = w << 5;

    const uint32_t sQ = smem_u32(Qs);
    const uint32_t sK = smem_u32(Ks);
    const uint32_t sV = smem_u32(Vs);
    const uint32_t sP = smem_u32(Ps);
    const uint32_t KVSTEP = (uint32_t)(64 * PW2) * 2u;

    const int arow = (lane & 7) + ((lane >> 3) & 1) * 8;
    const int acol = ((lane >> 4) & 1) * 8;
    const int brow = (lane & 7) + ((lane >> 4) & 1) * 8;
    const int bcol = ((lane >> 3) & 1) * 8;
    const int vrow = (lane & 7) + ((lane >> 3) & 1) * 8;
    const int vcol = ((lane >> 4) & 1) * 8;

    uint32_t qoff[2], koff[4], voff[4];
#pragma unroll
    for (int mt = 0; mt < 2; ++mt)
        qoff[mt] = (uint32_t)((rw + mt * 16 + arow) * PW2 + acol) * 2u;
#pragma unroll
    for (int p = 0; p < 4; ++p) {
        koff[p] = (uint32_t)((p * 16 + brow) * PW2 + bcol) * 2u;
        voff[p] = (uint32_t)(vrow * PW2 + p * 16 + vcol) * 2u;
    }

    int krow[4], kcol[4];
    uint32_t kdst[4];
#pragma unroll
    for (int i = 0; i < 4; ++i) {
        const int L = tid + (i << 7);
        krow[i] = L >> 3;
        kcol[i] = (L & 7) << 3;
        kdst[i] = (uint32_t)(krow[i] * PW2 + kcol[i]) * 2u;
    }

    // Prologue: stage Q + K/V tile 0
#pragma unroll
    for (int i = 0; i < 8; ++i) {
        const int L = tid + (i << 7);
        const int row = L >> 3;
        const int col = (L & 7) << 3;
        cpasync16(sQ + (uint32_t)(row * PW2 + col) * 2u,
                  Qg + ((size_t)(q0 + row) << 6) + col);
    }
#pragma unroll
    for (int i = 0; i < 4; ++i) {
        cpasync16(sK + kdst[i], Kg + ((size_t)krow[i] << 6) + kcol[i]);
        cpasync16(sV + kdst[i], Vg + ((size_t)krow[i] << 6) + kcol[i]);
    }
    CP_COMMIT();

    float o[2][8][4];
#pragma unroll
    for (int mt = 0; mt < 2; ++mt)
#pragma unroll
        for (int nt = 0; nt < 8; ++nt)
#pragma unroll
            for (int c = 0; c < 4; ++c) o[mt][nt][c] = 0.0f;
    float mrow[2][2], lrow[2][2];
#pragma unroll
    for (int mt = 0; mt < 2; ++mt) {
        mrow[mt][0] = -1e30f; mrow[mt][1] = -1e30f;
        lrow[mt][0] = 0.0f;   lrow[mt][1] = 0.0f;
    }

    const int nkt = 2 * qt + 2;
#pragma unroll 1
    for (int kt = 0; kt < nkt; ++kt) {
        const int k0 = kt << 6;

        CP_WAIT0();
        __syncthreads();

        if (kt + 1 < nkt) {
            const uint32_t bb = (uint32_t)((kt + 1) & 1) * KVSTEP;
            const int kn = (kt + 1) << 6;
#pragma unroll
            for (int i = 0; i < 4; ++i) {
                cpasync16(sK + bb + kdst[i], Kg + ((size_t)(kn + krow[i]) << 6) + kcol[i]);
                cpasync16(sV + bb + kdst[i], Vg + ((size_t)(kn + krow[i]) << 6) + kcol[i]);
            }
            CP_COMMIT();
        }

        const uint32_t kBuf = sK + (uint32_t)(kt & 1) * KVSTEP;
        const uint32_t vBuf = sV + (uint32_t)(kt & 1) * KVSTEP;

        // Scores (log2 domain), K-fragment register double-buffer
        float acc[2][8][4];
#pragma unroll
        for (int mt = 0; mt < 2; ++mt)
#pragma unroll
            for (int nt = 0; nt < 8; ++nt)
#pragma unroll
                for (int c = 0; c < 4; ++c) acc[mt][nt][c] = 0.0f;

        uint32_t kq[2][4][4];
#pragma unroll
        for (int p = 0; p < 4; ++p) ldsm4(kq[0][p], kBuf + koff[p]);

#pragma unroll
        for (int ks = 0; ks < 4; ++ks) {
            const int cur = ks & 1;
            if (ks < 3) {
                const uint32_t kb2 = (uint32_t)((ks + 1) * 16) * 2u;
#pragma unroll
                for (int p = 0; p < 4; ++p) ldsm4(kq[cur ^ 1][p], kBuf + koff[p] + kb2);
            }
            const uint32_t kb = (uint32_t)(ks * 16) * 2u;
#pragma unroll
            for (int mt = 0; mt < 2; ++mt) {
                uint32_t aq[4];
                ldsm4(aq, sQ + qoff[mt] + kb);
#pragma unroll
                for (int nt = 0; nt < 8; ++nt)
                    mma_f16(acc[mt][nt], aq[0], aq[1], aq[2], aq[3],
                            kq[cur][nt >> 1][(nt & 1) * 2], kq[cur][nt >> 1][(nt & 1) * 2 + 1]);
            }
        }

        // Causal mask
        if (kt >= 2 * qt) {
#pragma unroll
            for (int mt = 0; mt < 2; ++mt) {
                const int row0 = q0 + rw + (mt << 4) + g;
                const int row1 = row0 + 8;
#pragma unroll
                for (int nt = 0; nt < 8; ++nt) {
#pragma unroll
                    for (int cc = 0; cc < 2; ++cc) {
                        const int col = k0 + nt * 8 + tg * 2 + cc;
                        if (col > row0) acc[mt][nt][cc]     = -1e30f;
                        if (col > row1) acc[mt][nt][cc + 2] = -1e30f;
                    }
                }
            }
        }

        // Register online softmax (log2 domain; quad shfl)
#pragma unroll
        for (int mt = 0; mt < 2; ++mt) {
            const int rA = rw + (mt << 4) + g;
            const int rB = rA + 8;
            float mx0 = -1e30f, mx1 = -1e30f;
#pragma unroll
            for (int nt = 0; nt < 8; ++nt) {
                mx0 = fmaxf(mx0, fmaxf(acc[mt][nt][0], acc[mt][nt][1]));
                mx1 = fmaxf(mx1, fmaxf(acc[mt][nt][2], acc[mt][nt][3]));
            }
            mx0 = fmaxf(mx0, __shfl_xor_sync(0xffffffffu, mx0, 1));
            mx0 = fmaxf(mx0, __shfl_xor_sync(0xffffffffu, mx0, 2));
            mx1 = fmaxf(mx1, __shfl_xor_sync(0xffffffffu, mx1, 1));
            mx1 = fmaxf(mx1, __shfl_xor_sync(0xffffffffu, mx1, 2));

            const float mn0 = fmaxf(mrow[mt][0], mx0);
            const float mn1 = fmaxf(mrow[mt][1], mx1);
            const float sc0 = ex2(mrow[mt][0] - mn0);
            const float sc1 = ex2(mrow[mt][1] - mn1);

            float rs0 = 0.0f, rs1 = 0.0f;
#pragma unroll
            for (int nt = 0; nt < 8; ++nt) {
                const float p00 = ex2(acc[mt][nt][0] - mn0);
                const float p01 = ex2(acc[mt][nt][1] - mn0);
                const float p10 = ex2(acc[mt][nt][2] - mn1);
                const float p11 = ex2(acc[mt][nt][3] - mn1);
                rs0 += p00 + p01;
                rs1 += p10 + p11;
                const int cb = nt * 8 + tg * 2;
                __half2 hA = __floats2half2_rn(p00, p01);
                __half2 hB = __floats2half2_rn(p10, p11);
                *(uint32_t*)&Ps[rA * PW2 + cb] = *(uint32_t*)&hA;
                *(uint32_t*)&Ps[rB * PW2 + cb] = *(uint32_t*)&hB;
            }
            rs0 += __shfl_xor_sync(0xffffffffu, rs0, 1);
            rs0 += __shfl_xor_sync(0xffffffffu, rs0, 2);
            rs1 += __shfl_xor_sync(0xffffffffu, rs1, 1);
            rs1 += __shfl_xor_sync(0xffffffffu, rs1, 2);

            lrow[mt][0] = lrow[mt][0] * sc0 + rs0;
            lrow[mt][1] = lrow[mt][1] * sc1 + rs1;
            mrow[mt][0] = mn0;
            mrow[mt][1] = mn1;

#pragma unroll
            for (int nt = 0; nt < 8; ++nt) {
                o[mt][nt][0] *= sc0; o[mt][nt][1] *= sc0;
                o[mt][nt][2] *= sc1; o[mt][nt][3] *= sc1;
            }
        }

        __syncwarp();

        // PV: V-fragment register double-buffer (trans loads)
        uint32_t vq[2][4][4];
#pragma unroll
        for (int p = 0; p < 4; ++p) ldsm4t(vq[0][p], vBuf + voff[p]);

#pragma unroll
        for (int js = 0; js < 4; ++js) {
            const int cur = js & 1;
            if (js < 3) {
                const uint32_t vb2 = (uint32_t)((js + 1) * 16 * PW2) * 2u;
#pragma unroll
                for (int p = 0; p < 4; ++p) ldsm4t(vq[cur ^ 1][p], vBuf + voff[p] + vb2);
            }
            const uint32_t jb = (uint32_t)(js * 16) * 2u;
#pragma unroll
            for (int mt = 0; mt < 2; ++mt) {
                uint32_t aq[4];
                ldsm4(aq, sP + qoff[mt] + jb);
#pragma unroll
                for (int nt = 0; nt < 8; ++nt)
                    mma_f16(o[mt][nt], aq[0], aq[1], aq[2], aq[3],
                            vq[cur][nt >> 1][(nt & 1) * 2], vq[cur][nt >> 1][(nt & 1) * 2 + 1]);
            }
        }
    }

    // Epilogue -> ctx fp16
    const int b = bh >> 4;
    const int h = bh & 15;
#pragma unroll
    for (int mt = 0; mt < 2; ++mt) {
        const int rA = rw + (mt << 4) + g;
        const int rB = rA + 8;
        const float invl0 = 1.0f / lrow[mt][0];
        const float invl1 = 1.0f / lrow[mt][1];
#pragma unroll
        for (int nt = 0; nt < 8; ++nt) {
            const int col = (h << 6) + nt * 8 + tg * 2;
            __half2 h0 = __floats2half2_rn(o[mt][nt][0] * invl0, o[mt][nt][1] * invl0);
            __half2 h1 = __floats2half2_rn(o[mt][nt][2] * invl1, o[mt][nt][3] * invl1);
            *(uint32_t*)&g_ctx[((size_t)(b * S_ + q0 + rA)) * D_ + col] = *(uint32_t*)&h0;
            *(uint32_t*)&g_ctx[((size_t)(b * S_ + q0 + rB)) * D_ + col] = *(uint32_t*)&h1;
        }
    }
}

// ---------------------------------------------------------------------------
// Host launcher
// ---------------------------------------------------------------------------
extern "C" void kernel_launch(void* const* d_in, const int* in_sizes, int n_in,
                              void* d_out, int out_size)
{
    const float* x   = (const float*)d_in[0];
    const int*   pos = (const int*)  d_in[1];
    const float* Wq  = (const float*)d_in[2];
    const float* Wk  = (const float*)d_in[3];
    const float* Wv  = (const float*)d_in[4];
    const float* Wo  = (const float*)d_in[5];
    float* out = (float*)d_out;

    const int PROJ_SMEM = 4 * PSTG_H * sizeof(__half);                          // 73728 B
    const int ATTN_SMEM = (128 + 2 * 64 + 2 * 64 + 128) * PW2 * sizeof(__half); // 73728 B

    cudaFuncSetAttribute(qkv_gemm_kernel,   cudaFuncAttributeMaxDynamicSharedMemorySize, PROJ_SMEM);
    cudaFuncSetAttribute(oproj_gemm_kernel, cudaFuncAttributeMaxDynamicSharedMemorySize, PROJ_SMEM);
    cudaFuncSetAttribute(attn_kernel,       cudaFuncAttributeMaxDynamicSharedMemorySize, ATTN_SMEM);

    const int PRE_CTAS = (XN4 + 4 * WN4) / 256;   // 12288
    preconv_kernel<<<PRE_CTAS, 256>>>(x, Wq, Wk, Wv, Wo);
    qkv_gemm_kernel<<<dim3(D_ / 128, (B_ * S_) / 128, 3), 256, PROJ_SMEM>>>(pos);
    attn_kernel<<<dim3(B_ * H_, S_ / 128), 128, ATTN_SMEM>>>();
    oproj_gemm_kernel<<<dim3(D_ / 128, (B_ * S_) / 128), 256, PROJ_SMEM>>>(out);
}

// round 17
// speedup vs baseline: 1.1262x; 1.0306x over previous
#include <cuda_runtime.h>
#include <cuda_fp16.h>
#include <math.h>
#include <stdint.h>

#define B_  4
#define S_  2048
#define D_  1024
#define H_  16
#define DH_ 64

// fp16 operand buffers
__device__ __half g_q[(size_t)B_ * H_ * S_ * DH_];    // pre-scaled by QSCALE
__device__ __half g_k[(size_t)B_ * H_ * S_ * DH_];
__device__ __half g_v[(size_t)B_ * H_ * S_ * DH_];
__device__ __half g_ctx[(size_t)B_ * S_ * D_];
__device__ __half g_xh[(size_t)B_ * S_ * D_];
__device__ __half g_wqh[(size_t)D_ * D_];
__device__ __half g_wkh[(size_t)D_ * D_];
__device__ __half g_wvh[(size_t)D_ * D_];
__device__ __half g_woh[(size_t)D_ * D_];

__device__ __forceinline__ float ex2(float x) {
    float r;
    asm("ex2.approx.f32 %0, %1;" : "=f"(r) : "f"(x));
    return r;
}

__device__ __forceinline__ uint32_t ex2h2(uint32_t x) {
    uint32_t r;
    asm("ex2.approx.f16x2 %0, %1;" : "=r"(r) : "r"(x));
    return r;
}

__device__ __forceinline__ uint32_t smem_u32(const void* p) {
    uint32_t a;
    asm("{ .reg .u64 t; cvta.to.shared.u64 t, %1; cvt.u32.u64 %0, t; }" : "=r"(a) : "l"(p));
    return a;
}

__device__ __forceinline__ void mma_f16(float c[4], uint32_t a0, uint32_t a1,
                                        uint32_t a2, uint32_t a3,
                                        uint32_t b0, uint32_t b1) {
    asm volatile(
        "mma.sync.aligned.m16n8k16.row.col.f32.f16.f16.f32 "
        "{%0,%1,%2,%3},{%4,%5,%6,%7},{%8,%9},{%0,%1,%2,%3};"
        : "+f"(c[0]), "+f"(c[1]), "+f"(c[2]), "+f"(c[3])
        : "r"(a0), "r"(a1), "r"(a2), "r"(a3), "r"(b0), "r"(b1));
}

__device__ __forceinline__ void ldsm4(uint32_t r[4], uint32_t addr) {
    asm volatile("ldmatrix.sync.aligned.m8n8.x4.shared.b16 {%0,%1,%2,%3}, [%4];"
                 : "=r"(r[0]), "=r"(r[1]), "=r"(r[2]), "=r"(r[3]) : "r"(addr));
}
__device__ __forceinline__ void ldsm4t(uint32_t r[4], uint32_t addr) {
    asm volatile("ldmatrix.sync.aligned.m8n8.x4.trans.shared.b16 {%0,%1,%2,%3}, [%4];"
                 : "=r"(r[0]), "=r"(r[1]), "=r"(r[2]), "=r"(r[3]) : "r"(addr));
}

__device__ __forceinline__ void cpasync16(uint32_t dst, const void* src) {
    asm volatile("cp.async.ca.shared.global [%0], [%1], 16;" :: "r"(dst), "l"(src) : "memory");
}
#define CP_COMMIT() asm volatile("cp.async.commit_group;" ::: "memory")
#define CP_WAIT0()  asm volatile("cp.async.wait_group 0;" ::: "memory")

// ---------------------------------------------------------------------------
// Pre-convert (flat grid): fp32 -> fp16 for x and the four weight matrices.
// ---------------------------------------------------------------------------
#define XN4 ((B_ * S_ * D_) / 4)
#define WN4 ((D_ * D_) / 4)

__global__ void __launch_bounds__(256) preconv_kernel(const float* __restrict__ x,
                                                      const float* __restrict__ wq,
                                                      const float* __restrict__ wk,
                                                      const float* __restrict__ wv,
                                                      const float* __restrict__ wo)
{
    const int idx = blockIdx.x * 256 + threadIdx.x;
    const float* src;
    __half* dst;
    int off;
    if (idx < XN4) {
        src = x; dst = g_xh; off = idx;
    } else {
        const int widx = idx - XN4;
        const int region = widx / WN4;
        off = widx - region * WN4;
        switch (region) {
            case 0:  src = wq; dst = g_wqh; break;
            case 1:  src = wk; dst = g_wkh; break;
            case 2:  src = wv; dst = g_wvh; break;
            default: src = wo; dst = g_woh; break;
        }
    }
    float4 v = ((const float4*)src)[off];
    __half2 h0 = __floats2half2_rn(v.x, v.y);
    __half2 h1 = __floats2half2_rn(v.z, v.w);
    uint2 u;
    u.x = *(uint32_t*)&h0;
    u.y = *(uint32_t*)&h1;
    ((uint2*)dst)[off] = u;
}

// ---------------------------------------------------------------------------
// FP16 GEMM (R14 version — measured fastest), ldmatrix-fed, 1-barrier
// 2-stage cp.async double buffering.
// ---------------------------------------------------------------------------
#define PBKH   64
#define PW2    72
#define PSTG_H (128 * PW2)
#define PNKH   (D_ / PBKH)

__device__ __forceinline__ void gemm_f16(const __half* __restrict__ A,
                                         const __half* __restrict__ W,
                                         float acc[4][4][4])
{
    extern __shared__ __half smh[];
    __half* Asm = smh;
    __half* Bsm = smh + 2 * PSTG_H;

    const int tid  = threadIdx.x;
    const int lane = tid & 31;
    const int w    = tid >> 5;
    const int wm   = (w & 1) * 64;
    const int wn   = (w >> 1) * 32;

    const uint32_t sA = smem_u32(Asm);
    const uint32_t sB = smem_u32(Bsm);

    const int arow = (lane & 7) + ((lane >> 3) & 1) * 8;
    const int acol = ((lane >> 4) & 1) * 8;
    const int brow = (lane & 7) + ((lane >> 4) & 1) * 8;
    const int bcol = ((lane >> 3) & 1) * 8;
    uint32_t aoff[4], boff[2];
#pragma unroll
    for (int mt = 0; mt < 4; ++mt)
        aoff[mt] = (uint32_t)((wm + mt * 16 + arow) * PW2 + acol) * 2u;
#pragma unroll
    for (int p = 0; p < 2; ++p)
        boff[p] = (uint32_t)((wn + p * 16 + brow) * PW2 + bcol) * 2u;

    int lrow[4], lcol[4];
    uint32_t ldst[4];
#pragma unroll
    for (int i = 0; i < 4; ++i) {
        const int L = tid + 256 * i;
        lrow[i] = L >> 3;
        lcol[i] = (L & 7) << 3;
        ldst[i] = (uint32_t)(lrow[i] * PW2 + lcol[i]) * 2u;
    }

#pragma unroll
    for (int mt = 0; mt < 4; ++mt)
#pragma unroll
        for (int nt = 0; nt < 4; ++nt)
#pragma unroll
            for (int c = 0; c < 4; ++c) acc[mt][nt][c] = 0.0f;

#pragma unroll
    for (int i = 0; i < 4; ++i) {
        cpasync16(sA + ldst[i], A + (size_t)lrow[i] * D_ + lcol[i]);
        cpasync16(sB + ldst[i], W + (size_t)lrow[i] * D_ + lcol[i]);
    }
    CP_COMMIT();

#pragma unroll 1
    for (int kc = 0; kc < PNKH; ++kc) {
        CP_WAIT0();
        __syncthreads();

        if (kc + 1 < PNKH) {
            const uint32_t bb = (uint32_t)(((kc + 1) & 1) * PSTG_H) * 2u;
            const int ko = (kc + 1) * PBKH;
#pragma unroll
            for (int i = 0; i < 4; ++i) {
                cpasync16(sA + bb + ldst[i], A + (size_t)lrow[i] * D_ + ko + lcol[i]);
                cpasync16(sB + bb + ldst[i], W + (size_t)lrow[i] * D_ + ko + lcol[i]);
            }
            CP_COMMIT();
        }

        const uint32_t aB = sA + (uint32_t)((kc & 1) * PSTG_H) * 2u;
        const uint32_t bB = sB + (uint32_t)((kc & 1) * PSTG_H) * 2u;

#pragma unroll
        for (int ks = 0; ks < 4; ++ks) {
            const uint32_t kb = (uint32_t)(ks * 16) * 2u;
            uint32_t bq[2][4];
            ldsm4(bq[0], bB + boff[0] + kb);
            ldsm4(bq[1], bB + boff[1] + kb);
#pragma unroll
            for (int mt = 0; mt < 4; ++mt) {
                uint32_t aq[4];
                ldsm4(aq, aB + aoff[mt] + kb);
                mma_f16(acc[mt][0], aq[0], aq[1], aq[2], aq[3], bq[0][0], bq[0][1]);
                mma_f16(acc[mt][1], aq[0], aq[1], aq[2], aq[3], bq[0][2], bq[0][3]);
                mma_f16(acc[mt][2], aq[0], aq[1], aq[2], aq[3], bq[1][0], bq[1][1]);
                mma_f16(acc[mt][3], aq[0], aq[1], aq[2], aq[3], bq[1][2], bq[1][3]);
            }
        }
    }
}

#define QSCALE 0.180336887f   // 0.125 * log2(e)

// ---------------------------------------------------------------------------
// Fused QKV projection + RoPE epilogue (fp16 out; q pre-scaled by QSCALE).
// ---------------------------------------------------------------------------
__global__ void __launch_bounds__(256, 2) qkv_gemm_kernel(const int* __restrict__ pos)
{
    __shared__ float s_inv[32];
    if (threadIdx.x < 32)
        s_inv[threadIdx.x] = powf(10000.0f, -((float)(threadIdx.x * 2)) / 64.0f);

    const int m0 = blockIdx.y << 7;
    const int n0 = blockIdx.x << 7;
    const __half* W = (blockIdx.z == 0) ? g_wqh : ((blockIdx.z == 1) ? g_wkh : g_wvh);
    __half* out    = (blockIdx.z == 0) ? g_q : ((blockIdx.z == 1) ? g_k : g_v);
    const bool doRope = (blockIdx.z < 2);
    const float oscale = (blockIdx.z == 0) ? QSCALE : 1.0f;

    float acc[4][4][4];
    gemm_f16(g_xh + (size_t)m0 * D_, W + (size_t)n0 * D_, acc);

    const int lane = threadIdx.x & 31;
    const int w    = threadIdx.x >> 5;
    const int wm   = (w & 1) * 64;
    const int wn   = (w >> 1) * 32;
    const int g    = lane >> 2;
    const int tg   = lane & 3;

#pragma unroll
    for (int mt = 0; mt < 4; ++mt) {
#pragma unroll
        for (int half = 0; half < 2; ++half) {
            const int m = m0 + wm + mt * 16 + g + half * 8;
            const int b = m >> 11;
            const int s = m & (S_ - 1);
            const float fpos = doRope ? (float)pos[b * S_ + s] : 0.0f;
#pragma unroll
            for (int nt = 0; nt < 4; ++nt) {
                const int n  = n0 + wn + nt * 8 + tg * 2;
                const int h  = n >> 6;
                const int dh = n & 63;
                float vx = acc[mt][nt][half * 2 + 0];
                float vy = acc[mt][nt][half * 2 + 1];
                if (doRope) {
                    const float ang = fpos * s_inv[dh >> 1];
                    float sn, cs;
                    sincosf(ang, &sn, &cs);
                    const float rx = vx * cs - vy * sn;
                    const float ry = vx * sn + vy * cs;
                    vx = rx; vy = ry;
                }
                vx *= oscale; vy *= oscale;
                __half2 hv = __floats2half2_rn(vx, vy);
                *(uint32_t*)&out[((((size_t)b * H_ + h) * S_ + s) << 6) + dh] = *(uint32_t*)&hv;
            }
        }
    }
}

// ---------------------------------------------------------------------------
// Output projection (fp16 in, fp32 out).
// ---------------------------------------------------------------------------
__global__ void __launch_bounds__(256, 2) oproj_gemm_kernel(float* __restrict__ Out)
{
    const int m0 = blockIdx.y << 7;
    const int n0 = blockIdx.x << 7;

    float acc[4][4][4];
    gemm_f16(g_ctx + (size_t)m0 * D_, g_woh + (size_t)n0 * D_, acc);

    const int lane = threadIdx.x & 31;
    const int w    = threadIdx.x >> 5;
    const int wm   = (w & 1) * 64;
    const int wn   = (w >> 1) * 32;
    const int g    = lane >> 2;
    const int tg   = lane & 3;

#pragma unroll
    for (int mt = 0; mt < 4; ++mt) {
#pragma unroll
        for (int nt = 0; nt < 4; ++nt) {
            const int n = n0 + wn + nt * 8 + tg * 2;
#pragma unroll
            for (int half = 0; half < 2; ++half) {
                const int m = m0 + wm + mt * 16 + g + half * 8;
                float2 v;
                v.x = acc[mt][nt][half * 2 + 0];
                v.y = acc[mt][nt][half * 2 + 1];
                *(float2*)&Out[(size_t)m * D_ + n] = v;
            }
        }
    }
}

// ---------------------------------------------------------------------------
// Flash attention: R14 base + (a) Q fragments cached in registers across
// k-tiles, (b) P exponentials via ex2.approx.f16x2 (MUFU halved; P stored
// directly as packed fp16; row sums still fp32).
// ---------------------------------------------------------------------------
__global__ void __launch_bounds__(128, 2) attn_kernel()
{
    extern __shared__ __half smha[];
    __half* Qs = smha;                     // [128][72]
    __half* Ks = Qs + 128 * PW2;           // [2][64][72]
    __half* Vs = Ks + 2 * 64 * PW2;        // [2][64][72]
    __half* Ps = Vs + 2 * 64 * PW2;        // [128][72]

    const int bh = blockIdx.x;
    const int qt = gridDim.y - 1 - blockIdx.y;   // heavy tiles first
    const int q0 = qt << 7;

    const __half* Qg = g_q + ((size_t)bh * S_ << 6);
    const __half* Kg = g_k + ((size_t)bh * S_ << 6);
    const __half* Vg = g_v + ((size_t)bh * S_ << 6);

    const int tid  = threadIdx.x;
    const int lane = tid & 31;
    const int w    = tid >> 5;
    const int g    = lane >> 2;
    const int tg   = lane & 3;
    const int rw   = w << 5;

    const uint32_t sQ = smem_u32(Qs);
    const uint32_t sK = smem_u32(Ks);
    const uint32_t sV = smem_u32(Vs);
    const uint32_t sP = smem_u32(Ps);
    const uint32_t KVSTEP = (uint32_t)(64 * PW2) * 2u;

    const int arow = (lane & 7) + ((lane >> 3) & 1) * 8;
    const int acol = ((lane >> 4) & 1) * 8;
    const int brow = (lane & 7) + ((lane >> 4) & 1) * 8;
    const int bcol = ((lane >> 3) & 1) * 8;
    const int vrow = (lane & 7) + ((lane >> 3) & 1) * 8;
    const int vcol = ((lane >> 4) & 1) * 8;

    uint32_t qoff[2], koff[4], voff[4];
#pragma unroll
    for (int mt = 0; mt < 2; ++mt)
        qoff[mt] = (uint32_t)((rw + mt * 16 + arow) * PW2 + acol) * 2u;
#pragma unroll
    for (int p = 0; p < 4; ++p) {
        koff[p] = (uint32_t)((p * 16 + brow) * PW2 + bcol) * 2u;
        voff[p] = (uint32_t)(vrow * PW2 + p * 16 + vcol) * 2u;
    }

    int krow[4], kcol[4];
    uint32_t kdst[4];
#pragma unroll
    for (int i = 0; i < 4; ++i) {
        const int L = tid + (i << 7);
        krow[i] = L >> 3;
        kcol[i] = (L & 7) << 3;
        kdst[i] = (uint32_t)(krow[i] * PW2 + kcol[i]) * 2u;
    }

    // Prologue: stage Q + K/V tile 0
#pragma unroll
    for (int i = 0; i < 8; ++i) {
        const int L = tid + (i << 7);
        const int row = L >> 3;
        const int col = (L & 7) << 3;
        cpasync16(sQ + (uint32_t)(row * PW2 + col) * 2u,
                  Qg + ((size_t)(q0 + row) << 6) + col);
    }
#pragma unroll
    for (int i = 0; i < 4; ++i) {
        cpasync16(sK + kdst[i], Kg + ((size_t)krow[i] << 6) + kcol[i]);
        cpasync16(sV + kdst[i], Vg + ((size_t)krow[i] << 6) + kcol[i]);
    }
    CP_COMMIT();

    float o[2][8][4];
#pragma unroll
    for (int mt = 0; mt < 2; ++mt)
#pragma unroll
        for (int nt = 0; nt < 8; ++nt)
#pragma unroll
            for (int c = 0; c < 4; ++c) o[mt][nt][c] = 0.0f;
    float mrow[2][2], lrow[2][2];
#pragma unroll
    for (int mt = 0; mt < 2; ++mt) {
        mrow[mt][0] = -1e30f; mrow[mt][1] = -1e30f;
        lrow[mt][0] = 0.0f;   lrow[mt][1] = 0.0f;
    }

    uint32_t qfrag[2][4][4];   // Q fragments: [mt][ks][reg], invariant over k-tiles

    const int nkt = 2 * qt + 2;
#pragma unroll 1
    for (int kt = 0; kt < nkt; ++kt) {
        const int k0 = kt << 6;

        CP_WAIT0();
        __syncthreads();

        if (kt == 0) {
            // Q now resident: load all fragments once
#pragma unroll
            for (int mt = 0; mt < 2; ++mt)
#pragma unroll
                for (int ks = 0; ks < 4; ++ks)
                    ldsm4(qfrag[mt][ks], sQ + qoff[mt] + (uint32_t)(ks * 16) * 2u);
        }

        if (kt + 1 < nkt) {
            const uint32_t bb = (uint32_t)((kt + 1) & 1) * KVSTEP;
            const int kn = (kt + 1) << 6;
#pragma unroll
            for (int i = 0; i < 4; ++i) {
                cpasync16(sK + bb + kdst[i], Kg + ((size_t)(kn + krow[i]) << 6) + kcol[i]);
                cpasync16(sV + bb + kdst[i], Vg + ((size_t)(kn + krow[i]) << 6) + kcol[i]);
            }
            CP_COMMIT();
        }

        const uint32_t kBuf = sK + (uint32_t)(kt & 1) * KVSTEP;
        const uint32_t vBuf = sV + (uint32_t)(kt & 1) * KVSTEP;

        // Scores (log2 domain)
        float acc[2][8][4];
#pragma unroll
        for (int mt = 0; mt < 2; ++mt)
#pragma unroll
            for (int nt = 0; nt < 8; ++nt)
#pragma unroll
                for (int c = 0; c < 4; ++c) acc[mt][nt][c] = 0.0f;

#pragma unroll
        for (int ks = 0; ks < 4; ++ks) {
            const uint32_t kb = (uint32_t)(ks * 16) * 2u;
            uint32_t kq[4][4];
#pragma unroll
            for (int p = 0; p < 4; ++p) ldsm4(kq[p], kBuf + koff[p] + kb);
#pragma unroll
            for (int mt = 0; mt < 2; ++mt) {
#pragma unroll
                for (int nt = 0; nt < 8; ++nt)
                    mma_f16(acc[mt][nt],
                            qfrag[mt][ks][0], qfrag[mt][ks][1],
                            qfrag[mt][ks][2], qfrag[mt][ks][3],
                            kq[nt >> 1][(nt & 1) * 2], kq[nt >> 1][(nt & 1) * 2 + 1]);
            }
        }

        // Causal mask
        if (kt >= 2 * qt) {
#pragma unroll
            for (int mt = 0; mt < 2; ++mt) {
                const int row0 = q0 + rw + (mt << 4) + g;
                const int row1 = row0 + 8;
#pragma unroll
                for (int nt = 0; nt < 8; ++nt) {
#pragma unroll
                    for (int cc = 0; cc < 2; ++cc) {
                        const int col = k0 + nt * 8 + tg * 2 + cc;
                        if (col > row0) acc[mt][nt][cc]     = -1e30f;
                        if (col > row1) acc[mt][nt][cc + 2] = -1e30f;
                    }
                }
            }
        }

        // Register online softmax (log2 domain; quad shfl; f16x2 exponentials)
#pragma unroll
        for (int mt = 0; mt < 2; ++mt) {
            const int rA = rw + (mt << 4) + g;
            const int rB = rA + 8;
            float mx0 = -1e30f, mx1 = -1e30f;
#pragma unroll
            for (int nt = 0; nt < 8; ++nt) {
                mx0 = fmaxf(mx0, fmaxf(acc[mt][nt][0], acc[mt][nt][1]));
                mx1 = fmaxf(mx1, fmaxf(acc[mt][nt][2], acc[mt][nt][3]));
            }
            mx0 = fmaxf(mx0, __shfl_xor_sync(0xffffffffu, mx0, 1));
            mx0 = fmaxf(mx0, __shfl_xor_sync(0xffffffffu, mx0, 2));
            mx1 = fmaxf(mx1, __shfl_xor_sync(0xffffffffu, mx1, 1));
            mx1 = fmaxf(mx1, __shfl_xor_sync(0xffffffffu, mx1, 2));

            const float mn0 = fmaxf(mrow[mt][0], mx0);
            const float mn1 = fmaxf(mrow[mt][1], mx1);
            const float sc0 = ex2(mrow[mt][0] - mn0);
            const float sc1 = ex2(mrow[mt][1] - mn1);

            float rs0 = 0.0f, rs1 = 0.0f;
#pragma unroll
            for (int nt = 0; nt < 8; ++nt) {
                __half2 hd0 = __floats2half2_rn(acc[mt][nt][0] - mn0, acc[mt][nt][1] - mn0);
                __half2 hd1 = __floats2half2_rn(acc[mt][nt][2] - mn1, acc[mt][nt][3] - mn1);
                const uint32_t up0 = ex2h2(*(uint32_t*)&hd0);
                const uint32_t up1 = ex2h2(*(uint32_t*)&hd1);
                const int cb = nt * 8 + tg * 2;
                *(uint32_t*)&Ps[rA * PW2 + cb] = up0;
                *(uint32_t*)&Ps[rB * PW2 + cb] = up1;
                const float2 f0 = __half22float2(*(const __half2*)&up0);
                const float2 f1 = __half22float2(*(const __half2*)&up1);
                rs0 += f0.x + f0.y;
                rs1 += f1.x + f1.y;
            }
            rs0 += __shfl_xor_sync(0xffffffffu, rs0, 1);
            rs0 += __shfl_xor_sync(0xffffffffu, rs0, 2);
            rs1 += __shfl_xor_sync(0xffffffffu, rs1, 1);
            rs1 += __shfl_xor_sync(0xffffffffu, rs1, 2);

            lrow[mt][0] = lrow[mt][0] * sc0 + rs0;
            lrow[mt][1] = lrow[mt][1] * sc1 + rs1;
            mrow[mt][0] = mn0;
            mrow[mt][1] = mn1;

#pragma unroll
            for (int nt = 0; nt < 8; ++nt) {
                o[mt][nt][0] *= sc0; o[mt][nt][1] *= sc0;
                o[mt][nt][2] *= sc1; o[mt][nt][3] *= sc1;
            }
        }

        __syncwarp();

        // PV: P via ldsm4, V via ldsm4t (trans)
#pragma unroll
        for (int js = 0; js < 4; ++js) {
            const uint32_t jb = (uint32_t)(js * 16) * 2u;
            const uint32_t vb = (uint32_t)(js * 16 * PW2) * 2u;
            uint32_t vq[4][4];
#pragma unroll
            for (int p = 0; p < 4; ++p) ldsm4t(vq[p], vBuf + voff[p] + vb);
#pragma unroll
            for (int mt = 0; mt < 2; ++mt) {
                uint32_t aq[4];
                ldsm4(aq, sP + qoff[mt] + jb);
#pragma unroll
                for (int nt = 0; nt < 8; ++nt)
                    mma_f16(o[mt][nt], aq[0], aq[1], aq[2], aq[3],
                            vq[nt >> 1][(nt & 1) * 2], vq[nt >> 1][(nt & 1) * 2 + 1]);
            }
        }
    }

    // Epilogue -> ctx fp16
    const int b = bh >> 4;
    const int h = bh & 15;
#pragma unroll
    for (int mt = 0; mt < 2; ++mt) {
        const int rA = rw + (mt << 4) + g;
        const int rB = rA + 8;
        const float invl0 = 1.0f / lrow[mt][0];
        const float invl1 = 1.0f / lrow[mt][1];
#pragma unroll
        for (int nt = 0; nt < 8; ++nt) {
            const int col = (h << 6) + nt * 8 + tg * 2;
            __half2 h0 = __floats2half2_rn(o[mt][nt][0] * invl0, o[mt][nt][1] * invl0);
            __half2 h1 = __floats2half2_rn(o[mt][nt][2] * invl1, o[mt][nt][3] * invl1);
            *(uint32_t*)&g_ctx[((size_t)(b * S_ + q0 + rA)) * D_ + col] = *(uint32_t*)&h0;
            *(uint32_t*)&g_ctx[((size_t)(b * S_ + q0 + rB)) * D_ + col] = *(uint32_t*)&h1;
        }
    }
}

// ---------------------------------------------------------------------------
// Host launcher
// ---------------------------------------------------------------------------
extern "C" void kernel_launch(void* const* d_in, const int* in_sizes, int n_in,
                              void* d_out, int out_size)
{
    const float* x   = (const float*)d_in[0];
    const int*   pos = (const int*)  d_in[1];
    const float* Wq  = (const float*)d_in[2];
    const float* Wk  = (const float*)d_in[3];
    const float* Wv  = (const float*)d_in[4];
    const float* Wo  = (const float*)d_in[5];
    float* out = (float*)d_out;

    const int PROJ_SMEM = 4 * PSTG_H * sizeof(__half);                          // 73728 B
    const int ATTN_SMEM = (128 + 2 * 64 + 2 * 64 + 128) * PW2 * sizeof(__half); // 73728 B

    cudaFuncSetAttribute(qkv_gemm_kernel,   cudaFuncAttributeMaxDynamicSharedMemorySize, PROJ_SMEM);
    cudaFuncSetAttribute(oproj_gemm_kernel, cudaFuncAttributeMaxDynamicSharedMemorySize, PROJ_SMEM);
    cudaFuncSetAttribute(attn_kernel,       cudaFuncAttributeMaxDynamicSharedMemorySize, ATTN_SMEM);

    const int PRE_CTAS = (XN4 + 4 * WN4) / 256;   // 12288
    preconv_kernel<<<PRE_CTAS, 256>>>(x, Wq, Wk, Wv, Wo);
    qkv_gemm_kernel<<<dim3(D_ / 128, (B_ * S_) / 128, 3), 256, PROJ_SMEM>>>(pos);
    attn_kernel<<<dim3(B_ * H_, S_ / 128), 128, ATTN_SMEM>>>();
    oproj_gemm_kernel<<<dim3(D_ / 128, (B_ * S_) / 128), 256, PROJ_SMEM>>>(out);
}